// round 14
// baseline (speedup 1.0000x reference)
#include <cuda_runtime.h>
#include <math.h>

#define R 512
#define KCLS 81
#define XFORM_CLIP 4.135166556742356f
#define IMW_M1 1332.0f
#define IMH_M1 799.0f
#define INIT_KEY 0x00000000FFFFFFFFull
// iou>0.5 <=> inter > sum2/3. Certain-yes / certain-no thresholds with ~1e-3
// relative margin (total fp rounding incl. the +1 pre-add is <1e-5 relative).
#define C_HI 0.33350f
#define C_LO 0.33317f
#define TPC 136   // 32x32 tiles in the 16x16-word lower triangle (incl diag)

__device__ unsigned long long g_keys[R];   // per-roi (score, ~class) keys
__device__ int g_flag;   // 1 => select block has reset g_keys this call
__device__ int g_ctr;    // finished class blocks this call

__device__ __forceinline__ void bbox_xform(const float* __restrict__ rois,
                                           const float* __restrict__ deltas,
                                           int r, int k,
                                           float& x1, float& y1,
                                           float& x2, float& y2) {
    float rx1 = rois[r * 4 + 0], ry1 = rois[r * 4 + 1];
    float rx2 = rois[r * 4 + 2], ry2 = rois[r * 4 + 3];
    float w = rx2 - rx1 + 1.0f, h = ry2 - ry1 + 1.0f;
    float cx = rx1 + 0.5f * w, cy = ry1 + 0.5f * h;
    const float* dp = deltas + r * (4 * KCLS) + k * 4;
    float dx = dp[0] / 10.0f;
    float dy = dp[1] / 10.0f;
    float dw = fminf(dp[2] / 5.0f, XFORM_CLIP);
    float dh = fminf(dp[3] / 5.0f, XFORM_CLIP);
    float pcx = dx * w + cx, pcy = dy * h + cy;
    float pw = expf(dw) * w, ph = expf(dh) * h;
    x1 = fminf(fmaxf(pcx - 0.5f * pw, 0.0f), IMW_M1);
    y1 = fminf(fmaxf(pcy - 0.5f * ph, 0.0f), IMH_M1);
    x2 = fminf(fmaxf(pcx + 0.5f * pw - 1.0f, 0.0f), IMW_M1);
    y2 = fminf(fmaxf(pcy + 0.5f * ph - 1.0f, 0.0f), IMH_M1);
}

// Hybrid bitonic sort of 512 (score desc, idx asc on ties) — the measured-
// fastest variant (R8): 35 in-warp stages via shfl, 10 cross-warp via smem.
__device__ __forceinline__ void bitonic_sort_512(float& rs, int& ri,
                                                 float* ss, int* si, int tid) {
    #pragma unroll
    for (int kk = 2; kk <= R; kk <<= 1) {
        int j = kk >> 1;
        for (; j >= 32; j >>= 1) {
            ss[tid] = rs; si[tid] = ri;
            __syncthreads();
            int p = tid ^ j;
            float os = ss[p]; int oi = si[p];
            bool mineFirst = (rs > os) || (rs == os && ri < oi);
            bool up = ((tid & kk) == 0);
            bool iAmLow = ((tid & j) == 0);
            bool keepMine = (up == iAmLow) ? mineFirst : !mineFirst;
            if (!keepMine) { rs = os; ri = oi; }
            __syncthreads();
        }
        for (; j > 0; j >>= 1) {
            float os = __shfl_xor_sync(0xFFFFFFFFu, rs, j);
            int   oi = __shfl_xor_sync(0xFFFFFFFFu, ri, j);
            bool mineFirst = (rs > os) || (rs == os && ri < oi);
            bool up = ((tid & kk) == 0);
            bool iAmLow = ((tid & j) == 0);
            bool keepMine = (up == iAmLow) ? mineFirst : !mineFirst;
            if (!keepMine) { rs = os; ri = oi; }
        }
    }
}

__global__ __launch_bounds__(R, 1)
void fused_kernel(const float* __restrict__ rois,
                  const float* __restrict__ deltas,
                  const float* __restrict__ scores,
                  float* __restrict__ out) {
    __shared__ float4   bo[R];          // sorted original boxes   (8 KB)
    __shared__ float    ar[R];          // areas                   (2 KB)
    __shared__ unsigned Tr[16][R];      // transposed mask Tr[w][p](32 KB)
    __shared__ union {
        struct { float ss[R]; int si[R]; } srt;   // sort scratch
        unsigned long long keys[R];               // select keys
    } u;                                //                         (4 KB)
    __shared__ unsigned s_unc[16];
    __shared__ unsigned ka[16], kb[16];
    __shared__ float    s_red[16];

    const int tid  = threadIdx.x;
    const int lane = tid & 31;
    const int wid  = tid >> 5;
    const int bid  = blockIdx.x;

    if (bid < KCLS - 1) {
        // ====================== class block (c = bid+1) =====================
        const int c = bid + 1;

        // Init: zero mask, flags, keep seed.
        #pragma unroll
        for (int w = 0; w < 16; ++w) Tr[w][tid] = 0u;
        if (tid < 16) { s_unc[tid] = 0u; ka[tid] = 0xFFFFFFFFu; }

        // Load class scores; block max for cls_valid.
        float rs = scores[tid * KCLS + c];
        int   ri = tid;
        {
            float m = rs;
            #pragma unroll
            for (int o = 16; o > 0; o >>= 1)
                m = fmaxf(m, __shfl_xor_sync(0xFFFFFFFFu, m, o));
            if (lane == 0) s_red[wid] = m;
        }
        __syncthreads();
        {
            float v = s_red[0];
            #pragma unroll
            for (int q = 1; q < 16; ++q) v = fmaxf(v, s_red[q]);
            if (!(v > 0.001f)) {
                if (tid == 0) { __threadfence(); atomicAdd(&g_ctr, 1); }
                return;
            }
        }

        // Stable sort (score desc, idx asc).
        bitonic_sort_512(rs, ri, u.srt.ss, u.srt.si, tid);

        // bbox transform at sorted position tid; store ORIGINAL box.
        {
            float x1, y1, x2, y2;
            bbox_xform(rois, deltas, ri, c, x1, y1, x2, y2);
            bo[tid] = make_float4(x1, y1, x2, y2);
            ar[tid] = (x2 - x1 + 1.0f) * (y2 - y1 + 1.0f);
        }
        __syncthreads();

        // Transposed mask build: tile (jw, iw), lane owns column j.
        for (int tile = wid; tile < TPC; tile += 16) {
            int jw = 0;
            while ((jw + 1) * (jw + 2) / 2 <= tile) jw++;
            const int iw = tile - jw * (jw + 1) / 2;

            const int j = (jw << 5) + lane;
            const float4 jb = bo[j];
            const float  jz = jb.z + 1.0f;    // same fl(x2+1) as validated path
            const float  jw_ = jb.w + 1.0f;
            const float  ja = ar[j];
            const int ibase = iw << 5;

            unsigned bits = 0u;
            bool anyU = false;

            if (iw < jw) {
                #pragma unroll 4
                for (int ii = 0; ii < 32; ++ii) {
                    float4 bI = bo[ibase + ii];   // broadcast LDS128
                    float aa  = ar[ibase + ii];
                    float xx1 = fmaxf(bI.x, jb.x);
                    float yy1 = fmaxf(bI.y, jb.y);
                    float xx2 = fminf(bI.z + 1.0f, jz);
                    float yy2 = fminf(bI.w + 1.0f, jw_);
                    float iwd = fmaxf(xx2 - xx1, 0.0f);
                    float ihd = fmaxf(yy2 - yy1, 0.0f);
                    float inter = iwd * ihd;
                    float sum2  = aa + ja;
                    bool pw = (inter > C_LO * sum2);
                    bits |= pw ? (1u << ii) : 0u;
                    anyU |= pw && (inter <= C_HI * sum2);
                }
            } else {                               // diagonal tile: need i<j
                #pragma unroll 4
                for (int ii = 0; ii < 32; ++ii) {
                    float4 bI = bo[ibase + ii];
                    float aa  = ar[ibase + ii];
                    float xx1 = fmaxf(bI.x, jb.x);
                    float yy1 = fmaxf(bI.y, jb.y);
                    float xx2 = fminf(bI.z + 1.0f, jz);
                    float yy2 = fminf(bI.w + 1.0f, jw_);
                    float iwd = fmaxf(xx2 - xx1, 0.0f);
                    float ihd = fmaxf(yy2 - yy1, 0.0f);
                    float inter = iwd * ihd;
                    float sum2  = aa + ja;
                    bool pw = (inter > C_LO * sum2) && (ii < lane);
                    bits |= pw ? (1u << ii) : 0u;
                    anyU |= pw && (inter <= C_HI * sum2);
                }
            }

            Tr[iw][j] = bits;                     // conflict-free STS
            unsigned uw = __ballot_sync(0xFFFFFFFFu, anyU);
            if (lane == 0 && uw) atomicOr(&s_unc[jw], uw);
        }
        __syncthreads();

        // Exact fixup of flagged band columns (warp w scans flag word w).
        {
            unsigned f = s_unc[wid];
            while (f) {
                int bbit = __ffs(f) - 1; f &= f - 1;
                int j = (wid << 5) + bbit;
                float4 bj = bo[j];
                float  aj = ar[j];
                for (int w2 = 0; w2 < 16; ++w2) {
                    int q = (w2 << 5) + lane;
                    float4 bq = bo[q];
                    float xx1 = fmaxf(bq.x, bj.x);
                    float yy1 = fmaxf(bq.y, bj.y);
                    float xx2 = fminf(bq.z, bj.z);
                    float yy2 = fminf(bq.w, bj.w);
                    float iwd = fmaxf(xx2 - xx1 + 1.0f, 0.0f);
                    float ihd = fmaxf(yy2 - yy1 + 1.0f, 0.0f);
                    float inter = iwd * ihd;
                    float denom = (ar[q] + aj) - inter;
                    float iou = inter / denom;            // exact div.rn
                    bool ov = (iou > 0.5f) && (q < j);
                    unsigned bits = __ballot_sync(0xFFFFFFFFu, ov);
                    if (lane == 0) Tr[w2][j] = bits;
                }
            }
        }
        __syncthreads();

        // Own suppressor row (conflict-free LDS across lanes).
        unsigned Tw[16];
        #pragma unroll
        for (int w = 0; w < 16; ++w) Tw[w] = Tr[w][tid];

        // Jacobi fixpoint: keep[p] = !(exists kept suppressor q<p).
        // Unique fixpoint == sequential greedy result.
        unsigned* cur = ka;
        unsigned* nxt = kb;
        while (true) {
            unsigned sup = 0u;
            #pragma unroll
            for (int w = 0; w < 16; ++w) sup |= cur[w] & Tw[w];
            unsigned word = __ballot_sync(0xFFFFFFFFu, sup == 0u);
            bool chg = false;
            if (lane == 0) {
                nxt[wid] = word;
                chg = (word != cur[wid]);
            }
            if (!__syncthreads_or(chg)) break;
            unsigned* t = cur; cur = nxt; nxt = t;
        }

        // POST_NMS_TOPN cap (first 300 kept) + fold into global keys.
        if (tid == 0) {
            while (*(volatile int*)&g_flag == 0) {}
        }
        __syncthreads();
        __threadfence();
        {
            unsigned* fin = nxt;   // last written pass == fixpoint
            int w = tid >> 5;
            int pre = 0;
            for (int q = 0; q < w; ++q) pre += __popc(fin[q]);
            pre += __popc(fin[w] & ((1u << (tid & 31)) - 1u));
            bool kept = ((fin[w] >> (tid & 31)) & 1u) && (pre < 300);
            if (kept) {
                unsigned long long key =
                    ((unsigned long long)__float_as_uint(rs) << 32) |
                    (unsigned long long)(0xFFFFFFFFu - (unsigned)c);
                atomicMax(&g_keys[ri], key);
            }
        }
        __threadfence();
        __syncthreads();
        if (tid == 0) atomicAdd(&g_ctr, 1);

    } else {
        // ========================= select block =============================
        g_keys[tid] = INIT_KEY;
        __threadfence();
        __syncthreads();
        if (tid == 0) *(volatile int*)&g_flag = 1;

        if (tid == 0) {
            while (*(volatile int*)&g_ctr < KCLS - 1) {}
        }
        __syncthreads();
        __threadfence();

        unsigned long long myk;
        int lbl;
        float sc;
        {
            unsigned long long g = *(volatile unsigned long long*)&g_keys[tid];
            unsigned sbits = (unsigned)(g >> 32);
            sc  = __uint_as_float(sbits);
            lbl = (int)(0xFFFFFFFFu - (unsigned)(g & 0xFFFFFFFFull));
            myk = ((unsigned long long)sbits << 32) |
                  (unsigned long long)(R - 1 - tid);
            u.keys[tid] = myk;
        }
        __syncthreads();

        int rank = 0;
        const ulonglong2* k2 = (const ulonglong2*)u.keys;
        #pragma unroll 8
        for (int q = 0; q < R / 2; ++q) {
            ulonglong2 v = k2[q];
            rank += (v.x > myk) + (v.y > myk);
        }

        if (rank < 100) {
            bool valid = sc > 0.001f;
            float x1, y1, x2, y2;
            bbox_xform(rois, deltas, tid, lbl, x1, y1, x2, y2);
            if (!valid) { sc = 0.0f; x1 = 0.0f; y1 = 0.0f; x2 = 0.0f; y2 = 0.0f; }

            out[rank * 5 + 0] = sc;
            out[rank * 5 + 1] = x1;
            out[rank * 5 + 2] = y1;
            out[rank * 5 + 3] = x2;
            out[rank * 5 + 4] = y2;
            out[500 + rank] = (float)lbl;
            out[600 + rank] = (float)tid;
        }
        __syncthreads();
        if (tid == 0) { g_ctr = 0; g_flag = 0; }   // rearm for next replay
    }
}

extern "C" void kernel_launch(void* const* d_in, const int* in_sizes, int n_in,
                              void* d_out, int out_size) {
    const float* rois   = (const float*)d_in[0];
    const float* deltas = (const float*)d_in[1];
    const float* scores = (const float*)d_in[2];
    float* out = (float*)d_out;

    fused_kernel<<<KCLS, R>>>(rois, deltas, scores, out);
}